// round 16
// baseline (speedup 1.0000x reference)
#include <cuda_runtime.h>
#include <cuda_fp16.h>
#include <cstdint>

#define S_LEN 1024
#define B_SZ  64
#define H_DIM 512

// Scratch (allocation-free rule: __device__ globals)
__device__ float  g_lin[(size_t)S_LEN * B_SZ * H_DIM];   // GEMM output / scan input
__device__ __half g_Ahi[(size_t)S_LEN * B_SZ * H_DIM];   // y0 hi (written by scan 1)
__device__ __half g_Alo[(size_t)S_LEN * B_SZ * H_DIM];   // y0 lo
__device__ __half g_Whi[2][H_DIM * H_DIM];               // W hi (pre-scaled)
__device__ __half g_Wlo[2][H_DIM * H_DIM];               // W lo (pre-scaled)
__device__ int    g_flags[2][128];                       // per-layer group counters

#define W_SCALE     1024.0f
#define W_SCALE_INV (1.0f / 1024.0f)

// ---------------------------------------------------------------------------
// helpers
// ---------------------------------------------------------------------------
__device__ __forceinline__ void mma_f16(float* d,
                                        uint32_t a0, uint32_t a1, uint32_t a2, uint32_t a3,
                                        uint32_t b0, uint32_t b1) {
    asm volatile(
        "mma.sync.aligned.m16n8k16.row.col.f32.f16.f16.f32 "
        "{%0,%1,%2,%3}, {%4,%5,%6,%7}, {%8,%9}, {%0,%1,%2,%3};\n"
        : "+f"(d[0]), "+f"(d[1]), "+f"(d[2]), "+f"(d[3])
        : "r"(a0), "r"(a1), "r"(a2), "r"(a3), "r"(b0), "r"(b1));
}

#define LDSM_X4(r0, r1, r2, r3, addr)                                          \
    asm volatile("ldmatrix.sync.aligned.m8n8.x4.shared.b16 {%0,%1,%2,%3}, [%4];" \
                 : "=r"(r0), "=r"(r1), "=r"(r2), "=r"(r3) : "r"(addr))

__device__ __forceinline__ uint32_t smem_u32(const void* p) {
    uint32_t a;
    asm("{ .reg .u64 t; cvta.to.shared.u64 t, %1; cvt.u32.u64 %0, t; }"
        : "=r"(a) : "l"(p));
    return a;
}

__device__ __forceinline__ void cp_async16(uint32_t dst, const void* src) {
    asm volatile("cp.async.cg.shared.global [%0], [%1], 16;"
                 :: "r"(dst), "l"(src) : "memory");
}

__device__ __forceinline__ uint32_t pack_h2(float a, float b) {
    __half2 h = __floats2half2_rn(a, b);
    return *reinterpret_cast<uint32_t*>(&h);
}

// split (x,y) into packed fp16 hi pair + fp16 lo pair
__device__ __forceinline__ void split2(float x, float y, uint32_t& hi, uint32_t& lo) {
    float hx = __half2float(__float2half_rn(x));
    float hy = __half2float(__float2half_rn(y));
    hi = pack_h2(hx, hy);
    lo = pack_h2(x - hx, y - hy);
}

__device__ __forceinline__ void wait_flag(const int* p, int target) {
    int v;
    while (true) {
        asm volatile("ld.acquire.gpu.b32 %0, [%1];" : "=r"(v) : "l"(p) : "memory");
        if (v >= target) return;
        __nanosleep(128);
    }
}

// compact swizzled sub-stage (BM=64, BK=32): rows of 64B, chunk ^= (row>>1)&3
#define ST_AHI      0
#define ST_ALO      4096
#define ST_WHI      8192
#define ST_WLO      12288
#define SUB_BYTES   16384
#define SMEM_L1     (2 * SUB_BYTES)   // 32768 (double buffer)
#define SMEM_L2     (3 * SUB_BYTES)   // 49152 (3-stage cp.async)

// ---------------------------------------------------------------------------
// prep: convert both W (pre-scaled hi/lo) + zero flags, one launch
// ---------------------------------------------------------------------------
__global__ void prep_kernel(const float* __restrict__ W0,
                            const float* __restrict__ W1) {
    int bid = blockIdx.x;
    if (bid < 512) {
        int layer = bid >> 8;                       // 0 or 1
        const float* W = layer ? W1 : W0;
        __half* whi = g_Whi[layer];
        __half* wlo = g_Wlo[layer];
        int i = (bid & 255) * 256 + threadIdx.x;    // over float4; 65536 per layer
        float4 v = reinterpret_cast<const float4*>(W)[i];
        uint32_t h0, l0, h1, l1;
        split2(v.x * W_SCALE, v.y * W_SCALE, h0, l0);
        split2(v.z * W_SCALE, v.w * W_SCALE, h1, l1);
        reinterpret_cast<uint2*>(whi)[i] = make_uint2(h0, h1);
        reinterpret_cast<uint2*>(wlo)[i] = make_uint2(l0, l1);
    } else {
        reinterpret_cast<int*>(g_flags)[threadIdx.x] = 0;
    }
}

// ---------------------------------------------------------------------------
// LDSM-fed MMA on one sub-stage (verified addressing) + epilogue
// 4 warps: wm = warp&1 (2 m-rows of 32), wn = warp>>1 (2 n-cols of 32)
// ---------------------------------------------------------------------------
struct LdsmCtx {
    uint32_t aRowTerm[2], aSwz[2], aKsel;
    uint32_t bRowTerm[2], bSwz[2], bKsel;
};

__device__ __forceinline__ void ldsm_init(LdsmCtx& cx, int wm, int wn, int lane) {
    int aRowIn = (lane & 7) + ((lane >> 3) & 1) * 8;
    cx.aKsel = (uint32_t)(lane >> 4);
#pragma unroll
    for (int m2 = 0; m2 < 2; m2++) {
        int row = wm * 32 + m2 * 16 + aRowIn;
        cx.aRowTerm[m2] = (uint32_t)row * 64;
        cx.aSwz[m2] = (row >> 1) & 3;
    }
    int bRowIn = (lane & 7) + ((lane >> 4) & 1) * 8;
    cx.bKsel = (uint32_t)((lane >> 3) & 1);
#pragma unroll
    for (int p = 0; p < 2; p++) {
        int row = wn * 32 + p * 16 + bRowIn;
        cx.bRowTerm[p] = (uint32_t)row * 64;
        cx.bSwz[p] = (row >> 1) & 3;
    }
}

__device__ __forceinline__ void gemm_mma_stage(uint32_t sb, const LdsmCtx& cx,
                                               float acc[2][4][4]) {
#pragma unroll
    for (int kk = 0; kk < 2; kk++) {
        uint32_t ah[2][4], al[2][4], bh[2][4], bl[2][4];
#pragma unroll
        for (int m2 = 0; m2 < 2; m2++) {
            uint32_t tail = cx.aRowTerm[m2] +
                ((((uint32_t)kk * 2 + cx.aKsel) ^ cx.aSwz[m2]) << 4);
            LDSM_X4(ah[m2][0], ah[m2][1], ah[m2][2], ah[m2][3], sb + ST_AHI + tail);
            LDSM_X4(al[m2][0], al[m2][1], al[m2][2], al[m2][3], sb + ST_ALO + tail);
        }
#pragma unroll
        for (int p = 0; p < 2; p++) {
            uint32_t tail = cx.bRowTerm[p] +
                ((((uint32_t)kk * 2 + cx.bKsel) ^ cx.bSwz[p]) << 4);
            LDSM_X4(bh[p][0], bh[p][1], bh[p][2], bh[p][3], sb + ST_WHI + tail);
            LDSM_X4(bl[p][0], bl[p][1], bl[p][2], bl[p][3], sb + ST_WLO + tail);
        }
#pragma unroll
        for (int m2 = 0; m2 < 2; m2++) {
#pragma unroll
            for (int nt = 0; nt < 4; nt++) {
                int p = nt >> 1, q = nt & 1;
                uint32_t bf0 = bh[p][2 * q], bf1 = bh[p][2 * q + 1];
                uint32_t bg0 = bl[p][2 * q], bg1 = bl[p][2 * q + 1];
                mma_f16(acc[m2][nt], al[m2][0], al[m2][1], al[m2][2], al[m2][3], bf0, bf1);
                mma_f16(acc[m2][nt], ah[m2][0], ah[m2][1], ah[m2][2], ah[m2][3], bg0, bg1);
                mma_f16(acc[m2][nt], ah[m2][0], ah[m2][1], ah[m2][2], ah[m2][3], bf0, bf1);
            }
        }
    }
}

__device__ __forceinline__ void gemm_epilogue(float* C, const float* bias,
                                              float acc[2][4][4],
                                              int m0, int n0, int wm, int wn,
                                              int lane) {
    int r = lane >> 2, c = lane & 3;
#pragma unroll
    for (int m2 = 0; m2 < 2; m2++) {
#pragma unroll
        for (int nt = 0; nt < 4; nt++) {
            int row = m0 + wm * 32 + m2 * 16 + r;
            int col = n0 + wn * 32 + (nt >> 1) * 16 + (nt & 1) * 8 + 2 * c;
            float bx = bias[col], by = bias[col + 1];
            *reinterpret_cast<float2*>(C + (size_t)row * H_DIM + col) = make_float2(
                fmaf(acc[m2][nt][0], W_SCALE_INV, bx),
                fmaf(acc[m2][nt][1], W_SCALE_INV, by));
            *reinterpret_cast<float2*>(C + (size_t)(row + 8) * H_DIM + col) = make_float2(
                fmaf(acc[m2][nt][2], W_SCALE_INV, bx),
                fmaf(acc[m2][nt][3], W_SCALE_INV, by));
        }
    }
}

// ---------------------------------------------------------------------------
// scan role: 4 warps per batch row (H split 4x128, 4 elems/lane), 128 threads
// flag target: 64 arrivals per 8-timestep group (8 m-tiles x 8 n-blocks)
// ---------------------------------------------------------------------------
__device__ __forceinline__ void scan_role(
    const float* __restrict__ rec, const float* __restrict__ gam,
    const float* __restrict__ bet, float* __restrict__ y_ext,
    float* __restrict__ hid, int to_y0, int layer,
    const int* __restrict__ flags, char* dynsm)
{
    const int S = S_LEN, B = B_SZ;
    int b = blockIdx.x;
    int warp = threadIdx.x >> 5, lane = threadIdx.x & 31;
    int c0 = warp * 128 + lane * 4;

    float2* part = reinterpret_cast<float2*>(dynsm);   // 8 x float2 (2 buffers)

    float4 rc4 = *reinterpret_cast<const float4*>(rec + c0);
    float4 ga4 = *reinterpret_cast<const float4*>(gam + c0);
    float4 bb4 = *reinterpret_cast<const float4*>(bet + c0);
    float rc[4] = {rc4.x, rc4.y, rc4.z, rc4.w};
    float ga[4] = {ga4.x, ga4.y, ga4.z, ga4.w};
    float bb[4] = {bb4.x, bb4.y, bb4.z, bb4.w};
    float h[4]  = {0.0f, 0.0f, 0.0f, 0.0f};

    const size_t stride = (size_t)B * H_DIM;
    const float*  lp  = g_lin + (size_t)b * H_DIM + c0;
    float*        ypf = to_y0 ? nullptr : (y_ext + (size_t)b * H_DIM + c0);
    __half*       yph = g_Ahi + (size_t)b * H_DIM + c0;
    __half*       ypl = g_Alo + (size_t)b * H_DIM + c0;

    wait_flag(&flags[0], 64);
    float4 cuA = __ldcg(reinterpret_cast<const float4*>(lp));
    float4 cuB = __ldcg(reinterpret_cast<const float4*>(lp + stride));

#define SCAN_STEP(scur, CU)                                                        \
  {                                                                                \
    h[0] = fmaf(rc[0], h[0], CU.x);                                                \
    h[1] = fmaf(rc[1], h[1], CU.y);                                                \
    h[2] = fmaf(rc[2], h[2], CU.z);                                                \
    h[3] = fmaf(rc[3], h[3], CU.w);                                                \
    {                                                                              \
      int sp = (scur) + 2;                                                         \
      if (sp < S && (sp & 7) == 0) wait_flag(&flags[sp >> 3], 64);                 \
      if (sp > S - 1) sp = S - 1;                                                  \
      CU = __ldcg(reinterpret_cast<const float4*>(lp + (size_t)sp * stride));      \
    }                                                                              \
    float sum = (h[0] + h[1]) + (h[2] + h[3]);                                     \
    float ssq = fmaf(h[0], h[0], h[1] * h[1]) + fmaf(h[2], h[2], h[3] * h[3]);     \
    _Pragma("unroll")                                                              \
    for (int off = 16; off >= 1; off >>= 1) {                                      \
      sum += __shfl_xor_sync(0xffffffffu, sum, off);                               \
      ssq += __shfl_xor_sync(0xffffffffu, ssq, off);                               \
    }                                                                              \
    float2* pb = part + (((scur) & 1) << 2);                                       \
    if (lane == 0) pb[warp] = make_float2(sum, ssq);                               \
    asm volatile("bar.sync 3, 128;" ::: "memory");                                 \
    float4 p0 = *reinterpret_cast<float4*>(pb);                                    \
    float4 p1 = *reinterpret_cast<float4*>(pb + 2);                                \
    sum = (p0.x + p0.z) + (p1.x + p1.z);                                           \
    ssq = (p0.y + p0.w) + (p1.y + p1.w);                                           \
    float mean = sum * (1.0f / H_DIM);                                             \
    float var  = fmaf(ssq, 1.0f / H_DIM, -mean * mean);                            \
    float inv  = rsqrtf(var + 1e-6f);                                              \
    _Pragma("unroll")                                                              \
    for (int j = 0; j < 4; j++) {                                                  \
      float o = fmaf((h[j] - mean) * inv, ga[j], bb[j]);                           \
      h[j] = fminf(fmaxf(o, 0.0f), 6.0f);                                          \
    }                                                                              \
    if (to_y0) {                                                                   \
      uint32_t h0, l0, h1, l1;                                                     \
      split2(h[0], h[1], h0, l0);                                                  \
      split2(h[2], h[3], h1, l1);                                                  \
      *reinterpret_cast<uint2*>(yph + (size_t)(scur) * stride) = make_uint2(h0, h1);\
      *reinterpret_cast<uint2*>(ypl + (size_t)(scur) * stride) = make_uint2(l0, l1);\
    } else {                                                                       \
      *reinterpret_cast<float4*>(ypf + (size_t)(scur) * stride) =                  \
          make_float4(h[0], h[1], h[2], h[3]);                                     \
    }                                                                              \
  }

    for (int s = 0; s < S; s += 2) {
        SCAN_STEP(s,     cuA);
        SCAN_STEP(s + 1, cuB);
    }
#undef SCAN_STEP

    // hiddens: hid[(b>>5)][2*(b&31)+layer][h] = h_last[b][h]
    float* hp = hid + (size_t)(b >> 5) * (B * H_DIM)
                    + (size_t)(2 * (b & 31) + layer) * H_DIM + c0;
    *reinterpret_cast<float4*>(hp) = make_float4(h[0], h[1], h[2], h[3]);
}

// ---------------------------------------------------------------------------
// LAYER 1: 128-thread blocks. GEMM tile 64x64 (1 timestep per m-tile).
// A = x (fp32, inline convert, swizzled STS); W pre-split cp.async; 2-stage.
// ---------------------------------------------------------------------------
__global__ __launch_bounds__(128, 4) void layer1_kernel(
    const float* __restrict__ x,
    const float* __restrict__ bias,
    const float* __restrict__ rec,
    const float* __restrict__ gam,
    const float* __restrict__ bet,
    float* __restrict__ hid)
{
    const int K = H_DIM;
    extern __shared__ __align__(16) char dynsm[];

    if (blockIdx.x < 64) {
        scan_role(rec, gam, bet, nullptr, hid, /*to_y0=*/1, /*layer=*/0,
                  g_flags[0], dynsm);
        return;
    }

    // =================== GEMM role ===================
    uint32_t smb = smem_u32(dynsm);

    int gb = blockIdx.x - 64;
    int nb = gb & 7;            // n fastest -> A-slice reuse in L2
    int mt = gb >> 3;           // m-tile == timestep
    int n0 = nb * 64, m0 = mt * 64;

    int tid  = threadIdx.x;
    int warp = tid >> 5, lane = tid & 31;
    int wm = warp & 1, wn = warp >> 1;

    float acc[2][4][4];
#pragma unroll
    for (int m2 = 0; m2 < 2; m2++)
#pragma unroll
        for (int nt = 0; nt < 4; nt++)
#pragma unroll
            for (int i = 0; i < 4; i++) acc[m2][nt][i] = 0.0f;

    const float*  Ab    = x + (size_t)m0 * K;
    const __half* Whi_b = g_Whi[0] + (size_t)n0 * K;
    const __half* Wlo_b = g_Wlo[0] + (size_t)n0 * K;

    LdsmCtx cx;
    ldsm_init(cx, wm, wn, lane);

    // W loader: 64 rows x 4 chunks = 256 chunks; 2 per thread
    int w_row = tid >> 1;
    int w_cb  = (tid & 1) * 2;
    uint32_t w_swz = (uint32_t)((w_row >> 1) & 3);
    uint32_t w_dst0 = (uint32_t)w_row * 64 + ((((uint32_t)w_cb    ) ^ w_swz) << 4);
    uint32_t w_dst1 = (uint32_t)w_row * 64 + ((((uint32_t)w_cb + 1) ^ w_swz) << 4);

    auto load_stage = [&](int sidx, int kt) {
        uint32_t sb = smb + (uint32_t)sidx * SUB_BYTES;
        // A: 64 rows x 32 fp32 = 512 float4; 4 per thread, inline split
#pragma unroll
        for (int i = 0; i < 4; i++) {
            int idx = tid + i * 128;
            int row = idx >> 3;
            int c4  = idx & 7;
            float4 v = *reinterpret_cast<const float4*>(Ab + (size_t)row * K + kt + c4 * 4);
            uint32_t h0, l0, h1, l1;
            split2(v.x, v.y, h0, l0);
            split2(v.z, v.w, h1, l1);
            uint32_t dst = (uint32_t)row * 64 +
                ((((uint32_t)(c4 >> 1)) ^ ((uint32_t)(row >> 1) & 3)) << 4) +
                (uint32_t)(c4 & 1) * 8;
            asm volatile("st.shared.v2.b32 [%0], {%1, %2};"
                         :: "r"(sb + ST_AHI + dst), "r"(h0), "r"(h1) : "memory");
            asm volatile("st.shared.v2.b32 [%0], {%1, %2};"
                         :: "r"(sb + ST_ALO + dst), "r"(l0), "r"(l1) : "memory");
        }
        size_t srcW = (size_t)w_row * K + kt + w_cb * 8;
        cp_async16(sb + ST_WHI + w_dst0, Whi_b + srcW);
        cp_async16(sb + ST_WHI + w_dst1, Whi_b + srcW + 8);
        cp_async16(sb + ST_WLO + w_dst0, Wlo_b + srcW);
        cp_async16(sb + ST_WLO + w_dst1, Wlo_b + srcW + 8);
        asm volatile("cp.async.commit_group;" ::: "memory");
    };

    load_stage(0, 0);
    asm volatile("cp.async.wait_group 0;" ::: "memory");
    __syncthreads();

    int buf = 0;
    for (int it = 0; it < 16; ++it) {
        if (it < 15) load_stage(buf ^ 1, (it + 1) * 32);
        gemm_mma_stage(smb + (uint32_t)buf * SUB_BYTES, cx, acc);
        if (it < 15) asm volatile("cp.async.wait_group 0;" ::: "memory");
        __syncthreads();
        buf ^= 1;
    }

    gemm_epilogue(g_lin, bias, acc, m0, n0, wm, wn, lane);

    __syncthreads();
    if (tid == 0) {
        __threadfence();
        atomicAdd(&g_flags[0][mt >> 3], 1);  // 8 m-tiles x 8 n-blocks = 64
    }
}

// ---------------------------------------------------------------------------
// LAYER 2: 128-thread blocks. A = y0 halves; all operands cp.async, 3-stage.
// ---------------------------------------------------------------------------
__global__ __launch_bounds__(128, 4) void layer2_kernel(
    const float* __restrict__ bias,
    const float* __restrict__ rec,
    const float* __restrict__ gam,
    const float* __restrict__ bet,
    float* __restrict__ y_out,
    float* __restrict__ hid)
{
    const int K = H_DIM;
    extern __shared__ __align__(16) char dynsm[];

    if (blockIdx.x < 64) {
        scan_role(rec, gam, bet, y_out, hid, /*to_y0=*/0, /*layer=*/1,
                  g_flags[1], dynsm);
        return;
    }

    // =================== GEMM role ===================
    uint32_t smb = smem_u32(dynsm);

    int gb = blockIdx.x - 64;
    int nb = gb & 7;
    int mt = gb >> 3;
    int n0 = nb * 64, m0 = mt * 64;

    int tid  = threadIdx.x;
    int warp = tid >> 5, lane = tid & 31;
    int wm = warp & 1, wn = warp >> 1;

    float acc[2][4][4];
#pragma unroll
    for (int m2 = 0; m2 < 2; m2++)
#pragma unroll
        for (int nt = 0; nt < 4; nt++)
#pragma unroll
            for (int i = 0; i < 4; i++) acc[m2][nt][i] = 0.0f;

    const __half* Ahi_b = g_Ahi + (size_t)m0 * K;
    const __half* Alo_b = g_Alo + (size_t)m0 * K;
    const __half* Whi_b = g_Whi[1] + (size_t)n0 * K;
    const __half* Wlo_b = g_Wlo[1] + (size_t)n0 * K;

    LdsmCtx cx;
    ldsm_init(cx, wm, wn, lane);

    // A and W loaders: 64 rows x 4 chunks each; 2 chunks per thread each
    int rrow = tid >> 1;
    int cb   = (tid & 1) * 2;
    uint32_t rswz = (uint32_t)((rrow >> 1) & 3);
    uint32_t dst0 = (uint32_t)rrow * 64 + ((((uint32_t)cb    ) ^ rswz) << 4);
    uint32_t dst1 = (uint32_t)rrow * 64 + ((((uint32_t)cb + 1) ^ rswz) << 4);

    auto issue_stage = [&](int sidx, int kt) {
        uint32_t sb = smb + (uint32_t)sidx * SUB_BYTES;
        size_t src = (size_t)rrow * K + kt + cb * 8;
        cp_async16(sb + ST_AHI + dst0, Ahi_b + src);
        cp_async16(sb + ST_AHI + dst1, Ahi_b + src + 8);
        cp_async16(sb + ST_ALO + dst0, Alo_b + src);
        cp_async16(sb + ST_ALO + dst1, Alo_b + src + 8);
        cp_async16(sb + ST_WHI + dst0, Whi_b + src);
        cp_async16(sb + ST_WHI + dst1, Whi_b + src + 8);
        cp_async16(sb + ST_WLO + dst0, Wlo_b + src);
        cp_async16(sb + ST_WLO + dst1, Wlo_b + src + 8);
        asm volatile("cp.async.commit_group;" ::: "memory");
    };

    issue_stage(0, 0);
    issue_stage(1, 32);

    int cur = 0;
    for (int it = 0; it < 16; ++it) {
        if (it < 15) asm volatile("cp.async.wait_group 1;" ::: "memory");
        else         asm volatile("cp.async.wait_group 0;" ::: "memory");
        __syncthreads();

        if (it < 14) {
            int nxt2 = cur + 2; if (nxt2 >= 3) nxt2 -= 3;
            issue_stage(nxt2, (it + 2) * 32);
        }

        gemm_mma_stage(smb + (uint32_t)cur * SUB_BYTES, cx, acc);
        cur = cur + 1; if (cur >= 3) cur -= 3;
    }

    gemm_epilogue(g_lin, bias, acc, m0, n0, wm, wn, lane);

    __syncthreads();
    if (tid == 0) {
        __threadfence();
        atomicAdd(&g_flags[1][mt >> 3], 1);  // 8 m-tiles x 8 n-blocks = 64
    }
}

// ---------------------------------------------------------------------------
// launcher
// ---------------------------------------------------------------------------
extern "C" void kernel_launch(void* const* d_in, const int* in_sizes, int n_in,
                              void* d_out, int out_size)
{
    (void)n_in; (void)out_size; (void)in_sizes;
    const float* x    = (const float*)d_in[0];
    const float* W0   = (const float*)d_in[1];
    const float* b0   = (const float*)d_in[2];
    const float* rec0 = (const float*)d_in[3];
    const float* g0   = (const float*)d_in[4];
    const float* be0  = (const float*)d_in[5];
    const float* W1   = (const float*)d_in[6];
    const float* b1   = (const float*)d_in[7];
    const float* rec1 = (const float*)d_in[8];
    const float* g1   = (const float*)d_in[9];
    const float* be1  = (const float*)d_in[10];

    float* out = (float*)d_out;
    float* hid = out + (size_t)S_LEN * B_SZ * H_DIM;

    const int GRID = 64 + S_LEN * (H_DIM / 64);  // 64 + 8192

    cudaFuncSetAttribute(layer1_kernel,
                         cudaFuncAttributeMaxDynamicSharedMemorySize, SMEM_L1);
    cudaFuncSetAttribute(layer2_kernel,
                         cudaFuncAttributeMaxDynamicSharedMemorySize, SMEM_L2);

    prep_kernel<<<513, 256>>>(W0, W1);
    layer1_kernel<<<GRID, 128, SMEM_L1>>>(x, b0, rec0, g0, be0, hid);
    layer2_kernel<<<GRID, 128, SMEM_L2>>>(b1, rec1, g1, be1, out, hid);
}

// round 17
// speedup vs baseline: 1.2375x; 1.2375x over previous
#include <cuda_runtime.h>
#include <cuda_fp16.h>
#include <cstdint>

#define S_LEN 1024
#define B_SZ  64
#define H_DIM 512

// Scratch (allocation-free rule: __device__ globals)
__device__ float  g_lin[(size_t)S_LEN * B_SZ * H_DIM];   // GEMM output / scan input
__device__ __half g_Ahi[(size_t)S_LEN * B_SZ * H_DIM];   // y0 hi (written by scan 1)
__device__ __half g_Alo[(size_t)S_LEN * B_SZ * H_DIM];   // y0 lo
__device__ __half g_Whi[2][H_DIM * H_DIM];               // W hi (pre-scaled)
__device__ __half g_Wlo[2][H_DIM * H_DIM];               // W lo (pre-scaled)
__device__ int    g_flags[2][128];                       // per-layer group counters

#define W_SCALE     1024.0f
#define W_SCALE_INV (1.0f / 1024.0f)

// ---------------------------------------------------------------------------
// helpers
// ---------------------------------------------------------------------------
__device__ __forceinline__ void mma_f16(float* d,
                                        uint32_t a0, uint32_t a1, uint32_t a2, uint32_t a3,
                                        uint32_t b0, uint32_t b1) {
    asm volatile(
        "mma.sync.aligned.m16n8k16.row.col.f32.f16.f16.f32 "
        "{%0,%1,%2,%3}, {%4,%5,%6,%7}, {%8,%9}, {%0,%1,%2,%3};\n"
        : "+f"(d[0]), "+f"(d[1]), "+f"(d[2]), "+f"(d[3])
        : "r"(a0), "r"(a1), "r"(a2), "r"(a3), "r"(b0), "r"(b1));
}

#define LDSM_X4(r0, r1, r2, r3, addr)                                          \
    asm volatile("ldmatrix.sync.aligned.m8n8.x4.shared.b16 {%0,%1,%2,%3}, [%4];" \
                 : "=r"(r0), "=r"(r1), "=r"(r2), "=r"(r3) : "r"(addr))

__device__ __forceinline__ uint32_t smem_u32(const void* p) {
    uint32_t a;
    asm("{ .reg .u64 t; cvta.to.shared.u64 t, %1; cvt.u32.u64 %0, t; }"
        : "=r"(a) : "l"(p));
    return a;
}

__device__ __forceinline__ void cp_async16(uint32_t dst, const void* src) {
    asm volatile("cp.async.cg.shared.global [%0], [%1], 16;"
                 :: "r"(dst), "l"(src) : "memory");
}

__device__ __forceinline__ uint32_t pack_h2(float a, float b) {
    __half2 h = __floats2half2_rn(a, b);
    return *reinterpret_cast<uint32_t*>(&h);
}

// split (x,y) into packed fp16 hi pair + fp16 lo pair
__device__ __forceinline__ void split2(float x, float y, uint32_t& hi, uint32_t& lo) {
    float hx = __half2float(__float2half_rn(x));
    float hy = __half2float(__float2half_rn(y));
    hi = pack_h2(hx, hy);
    lo = pack_h2(x - hx, y - hy);
}

__device__ __forceinline__ void wait_flag(const int* p, int target) {
    int v;
    while (true) {
        asm volatile("ld.acquire.gpu.b32 %0, [%1];" : "=r"(v) : "l"(p) : "memory");
        if (v >= target) return;
        __nanosleep(128);
    }
}

// swizzled stage (BM=128, BN=128, BK=32): rows of 64B, chunk ^= (row>>1)&3
#define ST_AHI      0
#define ST_ALO      8192
#define ST_WHI      16384
#define ST_WLO      24576
#define SUB_BYTES   32768
#define SMEM_L1     (2 * SUB_BYTES)   // 65536 (double buffer)
#define SMEM_L2     (3 * SUB_BYTES)   // 98304 (3-stage cp.async)

// ---------------------------------------------------------------------------
// prep: convert both W (pre-scaled hi/lo) + zero flags, one launch
// ---------------------------------------------------------------------------
__global__ void prep_kernel(const float* __restrict__ W0,
                            const float* __restrict__ W1) {
    int bid = blockIdx.x;
    if (bid < 512) {
        int layer = bid >> 8;                       // 0 or 1
        const float* W = layer ? W1 : W0;
        __half* whi = g_Whi[layer];
        __half* wlo = g_Wlo[layer];
        int i = (bid & 255) * 256 + threadIdx.x;    // over float4; 65536 per layer
        float4 v = reinterpret_cast<const float4*>(W)[i];
        uint32_t h0, l0, h1, l1;
        split2(v.x * W_SCALE, v.y * W_SCALE, h0, l0);
        split2(v.z * W_SCALE, v.w * W_SCALE, h1, l1);
        reinterpret_cast<uint2*>(whi)[i] = make_uint2(h0, h1);
        reinterpret_cast<uint2*>(wlo)[i] = make_uint2(l0, l1);
    } else {
        reinterpret_cast<int*>(g_flags)[threadIdx.x] = 0;
    }
}

// ---------------------------------------------------------------------------
// LDSM-fed MMA, warp tile 32x64: wm = warp&3 (m), wn = warp>>2 (n, 64 cols)
// B fragments streamed per 16-col p-tile to cap register pressure.
// ---------------------------------------------------------------------------
struct LdsmCtx {
    uint32_t aRowTerm[2], aSwz[2], aKsel;
    uint32_t bRowTerm[4], bSwz[4], bKsel;
};

__device__ __forceinline__ void ldsm_init(LdsmCtx& cx, int wm, int wn, int lane) {
    int aRowIn = (lane & 7) + ((lane >> 3) & 1) * 8;
    cx.aKsel = (uint32_t)(lane >> 4);
#pragma unroll
    for (int m2 = 0; m2 < 2; m2++) {
        int row = wm * 32 + m2 * 16 + aRowIn;
        cx.aRowTerm[m2] = (uint32_t)row * 64;
        cx.aSwz[m2] = (row >> 1) & 3;
    }
    int bRowIn = (lane & 7) + ((lane >> 4) & 1) * 8;
    cx.bKsel = (uint32_t)((lane >> 3) & 1);
#pragma unroll
    for (int p = 0; p < 4; p++) {
        int row = wn * 64 + p * 16 + bRowIn;
        cx.bRowTerm[p] = (uint32_t)row * 64;
        cx.bSwz[p] = (row >> 1) & 3;
    }
}

__device__ __forceinline__ void gemm_mma_stage(uint32_t sb, const LdsmCtx& cx,
                                               float acc[2][8][4]) {
#pragma unroll
    for (int kk = 0; kk < 2; kk++) {
        uint32_t ah[2][4], al[2][4];
#pragma unroll
        for (int m2 = 0; m2 < 2; m2++) {
            uint32_t tail = cx.aRowTerm[m2] +
                ((((uint32_t)kk * 2 + cx.aKsel) ^ cx.aSwz[m2]) << 4);
            LDSM_X4(ah[m2][0], ah[m2][1], ah[m2][2], ah[m2][3], sb + ST_AHI + tail);
            LDSM_X4(al[m2][0], al[m2][1], al[m2][2], al[m2][3], sb + ST_ALO + tail);
        }
#pragma unroll
        for (int p = 0; p < 4; p++) {
            uint32_t bh[4], bl[4];
            uint32_t tail = cx.bRowTerm[p] +
                ((((uint32_t)kk * 2 + cx.bKsel) ^ cx.bSwz[p]) << 4);
            LDSM_X4(bh[0], bh[1], bh[2], bh[3], sb + ST_WHI + tail);
            LDSM_X4(bl[0], bl[1], bl[2], bl[3], sb + ST_WLO + tail);
#pragma unroll
            for (int m2 = 0; m2 < 2; m2++) {
#pragma unroll
                for (int q = 0; q < 2; q++) {
                    float* a = acc[m2][p * 2 + q];
                    uint32_t bf0 = bh[2 * q], bf1 = bh[2 * q + 1];
                    uint32_t bg0 = bl[2 * q], bg1 = bl[2 * q + 1];
                    mma_f16(a, al[m2][0], al[m2][1], al[m2][2], al[m2][3], bf0, bf1);
                    mma_f16(a, ah[m2][0], ah[m2][1], ah[m2][2], ah[m2][3], bg0, bg1);
                    mma_f16(a, ah[m2][0], ah[m2][1], ah[m2][2], ah[m2][3], bf0, bf1);
                }
            }
        }
    }
}

__device__ __forceinline__ void gemm_epilogue(float* C, const float* bias,
                                              float acc[2][8][4],
                                              int m0, int n0, int wm, int wn,
                                              int lane) {
    int r = lane >> 2, c = lane & 3;
#pragma unroll
    for (int m2 = 0; m2 < 2; m2++) {
#pragma unroll
        for (int nt = 0; nt < 8; nt++) {
            int row = m0 + wm * 32 + m2 * 16 + r;
            int col = n0 + wn * 64 + (nt >> 1) * 16 + (nt & 1) * 8 + 2 * c;
            float bx = bias[col], by = bias[col + 1];
            *reinterpret_cast<float2*>(C + (size_t)row * H_DIM + col) = make_float2(
                fmaf(acc[m2][nt][0], W_SCALE_INV, bx),
                fmaf(acc[m2][nt][1], W_SCALE_INV, by));
            *reinterpret_cast<float2*>(C + (size_t)(row + 8) * H_DIM + col) = make_float2(
                fmaf(acc[m2][nt][2], W_SCALE_INV, bx),
                fmaf(acc[m2][nt][3], W_SCALE_INV, by));
        }
    }
}

// ---------------------------------------------------------------------------
// scan role: 4 warps per batch row (H split 4x128, 4 elems/lane)
// flag target: 16 arrivals per 8-timestep group (4 m-tiles x 4 n-blocks)
// ---------------------------------------------------------------------------
__device__ __forceinline__ void scan_role(
    const float* __restrict__ rec, const float* __restrict__ gam,
    const float* __restrict__ bet, float* __restrict__ y_ext,
    float* __restrict__ hid, int to_y0, int layer,
    const int* __restrict__ flags, char* dynsm)
{
    const int S = S_LEN, B = B_SZ;
    int b = blockIdx.x;
    int warp = threadIdx.x >> 5, lane = threadIdx.x & 31;
    int c0 = warp * 128 + lane * 4;

    float2* part = reinterpret_cast<float2*>(dynsm);   // 8 x float2 (2 buffers)

    float4 rc4 = *reinterpret_cast<const float4*>(rec + c0);
    float4 ga4 = *reinterpret_cast<const float4*>(gam + c0);
    float4 bb4 = *reinterpret_cast<const float4*>(bet + c0);
    float rc[4] = {rc4.x, rc4.y, rc4.z, rc4.w};
    float ga[4] = {ga4.x, ga4.y, ga4.z, ga4.w};
    float bb[4] = {bb4.x, bb4.y, bb4.z, bb4.w};
    float h[4]  = {0.0f, 0.0f, 0.0f, 0.0f};

    const size_t stride = (size_t)B * H_DIM;
    const float*  lp  = g_lin + (size_t)b * H_DIM + c0;
    float*        ypf = to_y0 ? nullptr : (y_ext + (size_t)b * H_DIM + c0);
    __half*       yph = g_Ahi + (size_t)b * H_DIM + c0;
    __half*       ypl = g_Alo + (size_t)b * H_DIM + c0;

    wait_flag(&flags[0], 16);
    float4 cuA = __ldcg(reinterpret_cast<const float4*>(lp));
    float4 cuB = __ldcg(reinterpret_cast<const float4*>(lp + stride));

#define SCAN_STEP(scur, CU)                                                        \
  {                                                                                \
    h[0] = fmaf(rc[0], h[0], CU.x);                                                \
    h[1] = fmaf(rc[1], h[1], CU.y);                                                \
    h[2] = fmaf(rc[2], h[2], CU.z);                                                \
    h[3] = fmaf(rc[3], h[3], CU.w);                                                \
    {                                                                              \
      int sp = (scur) + 2;                                                         \
      if (sp < S && (sp & 7) == 0) wait_flag(&flags[sp >> 3], 16);                 \
      if (sp > S - 1) sp = S - 1;                                                  \
      CU = __ldcg(reinterpret_cast<const float4*>(lp + (size_t)sp * stride));      \
    }                                                                              \
    float sum = (h[0] + h[1]) + (h[2] + h[3]);                                     \
    float ssq = fmaf(h[0], h[0], h[1] * h[1]) + fmaf(h[2], h[2], h[3] * h[3]);     \
    _Pragma("unroll")                                                              \
    for (int off = 16; off >= 1; off >>= 1) {                                      \
      sum += __shfl_xor_sync(0xffffffffu, sum, off);                               \
      ssq += __shfl_xor_sync(0xffffffffu, ssq, off);                               \
    }                                                                              \
    float2* pb = part + (((scur) & 1) << 2);                                       \
    if (lane == 0) pb[warp] = make_float2(sum, ssq);                               \
    asm volatile("bar.sync 3, 128;" ::: "memory");                                 \
    float4 p0 = *reinterpret_cast<float4*>(pb);                                    \
    float4 p1 = *reinterpret_cast<float4*>(pb + 2);                                \
    sum = (p0.x + p0.z) + (p1.x + p1.z);                                           \
    ssq = (p0.y + p0.w) + (p1.y + p1.w);                                           \
    float mean = sum * (1.0f / H_DIM);                                             \
    float var  = fmaf(ssq, 1.0f / H_DIM, -mean * mean);                            \
    float inv  = rsqrtf(var + 1e-6f);                                              \
    _Pragma("unroll")                                                              \
    for (int j = 0; j < 4; j++) {                                                  \
      float o = fmaf((h[j] - mean) * inv, ga[j], bb[j]);                           \
      h[j] = fminf(fmaxf(o, 0.0f), 6.0f);                                          \
    }                                                                              \
    if (to_y0) {                                                                   \
      uint32_t h0, l0, h1, l1;                                                     \
      split2(h[0], h[1], h0, l0);                                                  \
      split2(h[2], h[3], h1, l1);                                                  \
      *reinterpret_cast<uint2*>(yph + (size_t)(scur) * stride) = make_uint2(h0, h1);\
      *reinterpret_cast<uint2*>(ypl + (size_t)(scur) * stride) = make_uint2(l0, l1);\
    } else {                                                                       \
      *reinterpret_cast<float4*>(ypf + (size_t)(scur) * stride) =                  \
          make_float4(h[0], h[1], h[2], h[3]);                                     \
    }                                                                              \
  }

    for (int s = 0; s < S; s += 2) {
        SCAN_STEP(s,     cuA);
        SCAN_STEP(s + 1, cuB);
    }
#undef SCAN_STEP

    // hiddens: hid[(b>>5)][2*(b&31)+layer][h] = h_last[b][h]
    float* hp = hid + (size_t)(b >> 5) * (B * H_DIM)
                    + (size_t)(2 * (b & 31) + layer) * H_DIM + c0;
    *reinterpret_cast<float4*>(hp) = make_float4(h[0], h[1], h[2], h[3]);
}

// ---------------------------------------------------------------------------
// LAYER 1: tile 128x128. A = x (fp32 inline convert); W pre-split cp.async.
// 2-stage double buffer.
// ---------------------------------------------------------------------------
__global__ __launch_bounds__(256, 2) void layer1_kernel(
    const float* __restrict__ x,
    const float* __restrict__ bias,
    const float* __restrict__ rec,
    const float* __restrict__ gam,
    const float* __restrict__ bet,
    float* __restrict__ hid)
{
    const int K = H_DIM;
    extern __shared__ __align__(16) char dynsm[];

    if (blockIdx.x < 64) {
        if (threadIdx.x >= 128) return;
        scan_role(rec, gam, bet, nullptr, hid, /*to_y0=*/1, /*layer=*/0,
                  g_flags[0], dynsm);
        return;
    }

    // =================== GEMM role ===================
    uint32_t smb = smem_u32(dynsm);

    int gb = blockIdx.x - 64;
    int nb = gb & 3;            // n fastest -> A-slice reuse in L2
    int mt = gb >> 2;
    int n0 = nb * 128, m0 = mt * 128;

    int tid  = threadIdx.x;
    int warp = tid >> 5, lane = tid & 31;
    int wm = warp & 3, wn = warp >> 2;

    float acc[2][8][4];
#pragma unroll
    for (int m2 = 0; m2 < 2; m2++)
#pragma unroll
        for (int nt = 0; nt < 8; nt++)
#pragma unroll
            for (int i = 0; i < 4; i++) acc[m2][nt][i] = 0.0f;

    const float*  Ab    = x + (size_t)m0 * K;
    const __half* Whi_b = g_Whi[0] + (size_t)n0 * K;
    const __half* Wlo_b = g_Wlo[0] + (size_t)n0 * K;

    LdsmCtx cx;
    ldsm_init(cx, wm, wn, lane);

    // W loader: 128 rows x 4 chunks = 512 chunks; 2 hi + 2 lo per thread
    int w_row = tid >> 1;
    int w_cb  = (tid & 1) * 2;
    uint32_t w_swz = (uint32_t)((w_row >> 1) & 3);
    uint32_t w_dst0 = (uint32_t)w_row * 64 + ((((uint32_t)w_cb    ) ^ w_swz) << 4);
    uint32_t w_dst1 = (uint32_t)w_row * 64 + ((((uint32_t)w_cb + 1) ^ w_swz) << 4);

    auto load_stage = [&](int sidx, int kt) {
        uint32_t sb = smb + (uint32_t)sidx * SUB_BYTES;
        // A: 128 rows x 32 fp32 = 1024 float4; 4 per thread, inline split
#pragma unroll
        for (int i = 0; i < 4; i++) {
            int idx = tid + i * 256;
            int row = idx >> 3;
            int c4  = idx & 7;
            float4 v = *reinterpret_cast<const float4*>(Ab + (size_t)row * K + kt + c4 * 4);
            uint32_t h0, l0, h1, l1;
            split2(v.x, v.y, h0, l0);
            split2(v.z, v.w, h1, l1);
            uint32_t dst = (uint32_t)row * 64 +
                ((((uint32_t)(c4 >> 1)) ^ ((uint32_t)(row >> 1) & 3)) << 4) +
                (uint32_t)(c4 & 1) * 8;
            asm volatile("st.shared.v2.b32 [%0], {%1, %2};"
                         :: "r"(sb + ST_AHI + dst), "r"(h0), "r"(h1) : "memory");
            asm volatile("st.shared.v2.b32 [%0], {%1, %2};"
                         :: "r"(sb + ST_ALO + dst), "r"(l0), "r"(l1) : "memory");
        }
        size_t srcW = (size_t)w_row * K + kt + w_cb * 8;
        cp_async16(sb + ST_WHI + w_dst0, Whi_b + srcW);
        cp_async16(sb + ST_WHI + w_dst1, Whi_b + srcW + 8);
        cp_async16(sb + ST_WLO + w_dst0, Wlo_b + srcW);
        cp_async16(sb + ST_WLO + w_dst1, Wlo_b + srcW + 8);
        asm volatile("cp.async.commit_group;" ::: "memory");
    };

    load_stage(0, 0);
    asm volatile("cp.async.wait_group 0;" ::: "memory");
    __syncthreads();

    int buf = 0;
    for (int it = 0; it < 16; ++it) {
        if (it < 15) load_stage(buf ^ 1, (it + 1) * 32);
        gemm_mma_stage(smb + (uint32_t)buf * SUB_BYTES, cx, acc);
        if (it < 15) asm volatile("cp.async.wait_group 0;" ::: "memory");
        __syncthreads();
        buf ^= 1;
    }

    gemm_epilogue(g_lin, bias, acc, m0, n0, wm, wn, lane);

    __syncthreads();
    if (tid == 0) {
        __threadfence();
        atomicAdd(&g_flags[0][mt >> 2], 1);  // 4 m-tiles x 4 n-blocks = 16
    }
}

// ---------------------------------------------------------------------------
// LAYER 2: tile 128x128. A = y0 halves; all operands cp.async, 3-stage.
// ---------------------------------------------------------------------------
__global__ __launch_bounds__(256, 2) void layer2_kernel(
    const float* __restrict__ bias,
    const float* __restrict__ rec,
    const float* __restrict__ gam,
    const float* __restrict__ bet,
    float* __restrict__ y_out,
    float* __restrict__ hid)
{
    const int K = H_DIM;
    extern __shared__ __align__(16) char dynsm[];

    if (blockIdx.x < 64) {
        if (threadIdx.x >= 128) return;
        scan_role(rec, gam, bet, y_out, hid, /*to_y0=*/0, /*layer=*/1,
                  g_flags[1], dynsm);
        return;
    }

    // =================== GEMM role ===================
    uint32_t smb = smem_u32(dynsm);

    int gb = blockIdx.x - 64;
    int nb = gb & 3;
    int mt = gb >> 2;
    int n0 = nb * 128, m0 = mt * 128;

    int tid  = threadIdx.x;
    int warp = tid >> 5, lane = tid & 31;
    int wm = warp & 3, wn = warp >> 2;

    float acc[2][8][4];
#pragma unroll
    for (int m2 = 0; m2 < 2; m2++)
#pragma unroll
        for (int nt = 0; nt < 8; nt++)
#pragma unroll
            for (int i = 0; i < 4; i++) acc[m2][nt][i] = 0.0f;

    const __half* Ahi_b = g_Ahi + (size_t)m0 * K;
    const __half* Alo_b = g_Alo + (size_t)m0 * K;
    const __half* Whi_b = g_Whi[1] + (size_t)n0 * K;
    const __half* Wlo_b = g_Wlo[1] + (size_t)n0 * K;

    LdsmCtx cx;
    ldsm_init(cx, wm, wn, lane);

    // loaders: 128 rows x 4 chunks each; 2 hi + 2 lo per thread for A and W
    int rrow = tid >> 1;
    int cb   = (tid & 1) * 2;
    uint32_t rswz = (uint32_t)((rrow >> 1) & 3);
    uint32_t dst0 = (uint32_t)rrow * 64 + ((((uint32_t)cb    ) ^ rswz) << 4);
    uint32_t dst1 = (uint32_t)rrow * 64 + ((((uint32_t)cb + 1) ^ rswz) << 4);

    auto issue_stage = [&](int sidx, int kt) {
        uint32_t sb = smb + (uint32_t)sidx * SUB_BYTES;
        size_t src = (size_t)rrow * K + kt + cb * 8;
        cp_async16(sb + ST_AHI + dst0, Ahi_b + src);
        cp_async16(sb + ST_AHI + dst1, Ahi_b + src + 8);
        cp_async16(sb + ST_ALO + dst0, Alo_b + src);
        cp_async16(sb + ST_ALO + dst1, Alo_b + src + 8);
        cp_async16(sb + ST_WHI + dst0, Whi_b + src);
        cp_async16(sb + ST_WHI + dst1, Whi_b + src + 8);
        cp_async16(sb + ST_WLO + dst0, Wlo_b + src);
        cp_async16(sb + ST_WLO + dst1, Wlo_b + src + 8);
        asm volatile("cp.async.commit_group;" ::: "memory");
    };

    issue_stage(0, 0);
    issue_stage(1, 32);

    int cur = 0;
    for (int it = 0; it < 16; ++it) {
        if (it < 15) asm volatile("cp.async.wait_group 1;" ::: "memory");
        else         asm volatile("cp.async.wait_group 0;" ::: "memory");
        __syncthreads();

        if (it < 14) {
            int nxt2 = cur + 2; if (nxt2 >= 3) nxt2 -= 3;
            issue_stage(nxt2, (it + 2) * 32);
        }

        gemm_mma_stage(smb + (uint32_t)cur * SUB_BYTES, cx, acc);
        cur = cur + 1; if (cur >= 3) cur -= 3;
    }

    gemm_epilogue(g_lin, bias, acc, m0, n0, wm, wn, lane);

    __syncthreads();
    if (tid == 0) {
        __threadfence();
        atomicAdd(&g_flags[1][mt >> 2], 1);  // 4 m-tiles x 4 n-blocks = 16
    }
}

// ---------------------------------------------------------------------------
// launcher (no static guards; SetAttribute is idempotent)
// ---------------------------------------------------------------------------
extern "C" void kernel_launch(void* const* d_in, const int* in_sizes, int n_in,
                              void* d_out, int out_size)
{
    (void)n_in; (void)out_size; (void)in_sizes;
    const float* x    = (const float*)d_in[0];
    const float* W0   = (const float*)d_in[1];
    const float* b0   = (const float*)d_in[2];
    const float* rec0 = (const float*)d_in[3];
    const float* g0   = (const float*)d_in[4];
    const float* be0  = (const float*)d_in[5];
    const float* W1   = (const float*)d_in[6];
    const float* b1   = (const float*)d_in[7];
    const float* rec1 = (const float*)d_in[8];
    const float* g1   = (const float*)d_in[9];
    const float* be1  = (const float*)d_in[10];

    float* out = (float*)d_out;
    float* hid = out + (size_t)S_LEN * B_SZ * H_DIM;

    const int GRID = 64 + (S_LEN * B_SZ / 128) * (H_DIM / 128);  // 64 + 2048

    cudaFuncSetAttribute(layer1_kernel,
                         cudaFuncAttributeMaxDynamicSharedMemorySize, SMEM_L1);
    cudaFuncSetAttribute(layer2_kernel,
                         cudaFuncAttributeMaxDynamicSharedMemorySize, SMEM_L2);

    prep_kernel<<<513, 256>>>(W0, W1);
    layer1_kernel<<<GRID, 256, SMEM_L1>>>(x, b0, rec0, g0, be0, hid);
    layer2_kernel<<<GRID, 256, SMEM_L2>>>(b1, rec1, g1, be1, out, hid);
}